// round 6
// baseline (speedup 1.0000x reference)
#include <cuda_runtime.h>
#include <cuda_bf16.h>
#include <cstdint>

// out[b, o] = bias[o] + sum over UNIQUE (i0,i1) pairs in batch row b of
//             W[i0*350 + i1, o]
//
// Inputs (metadata order):
//   d_in[0]: x    int32  [32, 200, 3]   (b, i0, i1)
//   d_in[1]: W    float  [2150400, 5]
//   d_in[2]: b    float  [5]
// Output: float [32, 5]
//
// One WARP per batch row: no __syncthreads, no global atomics, no cross-warp
// skew. 7 hits per lane, all W gathers front-batched (MLP ~35/thread).

#define NB      32
#define NHITS   200
#define D1      350
#define OUT     5
#define HPT     7              // ceil(200 / 32) hits per thread
#define HASH_SZ 512
#define HASH_MASK (HASH_SZ - 1)

__global__ void __launch_bounds__(32, 1)
prtnn_kernel(const int* __restrict__ x,
             const float* __restrict__ W,
             const float* __restrict__ bias,
             float* __restrict__ out)
{
    const int b    = blockIdx.x;
    const int lane = threadIdx.x;          // 0..31

    __shared__ int table[HASH_SZ];

    // ---- front-batch ALL independent loads first (maximize MLP) ----

    // x indices: lane handles hits {lane, lane+32, ..., lane+192}
    int   fs[HPT];
    bool  valid[HPT];
    #pragma unroll
    for (int i = 0; i < HPT; ++i) {
        const int h = lane + 32 * i;
        valid[i] = (h < NHITS);
        if (valid[i]) {
            const int* xp = x + ((size_t)b * NHITS + h) * 3;
            fs[i] = __ldg(xp + 1) * D1 + __ldg(xp + 2);
        } else {
            fs[i] = 0;                     // safe dummy address, masked later
        }
    }

    // bias: lanes 0..4 each grab their own (overlaps with everything)
    float bv = (lane < OUT) ? __ldg(bias + lane) : 0.0f;

    // hash table init: 128 int4 stores / 32 lanes = 4 vector stores per lane
    {
        int4* tb = reinterpret_cast<int4*>(table);
        const int4 m1 = make_int4(-1, -1, -1, -1);
        #pragma unroll
        for (int i = 0; i < HASH_SZ / 4 / 32; ++i)
            tb[lane + 32 * i] = m1;
    }
    __syncwarp();                          // table visible to warp before CAS

    // ---- speculative W-row gathers (35 independent LDGs in flight) ----
    float wv[HPT][OUT];
    #pragma unroll
    for (int i = 0; i < HPT; ++i) {
        const float* w = W + fs[i] * OUT;  // fs*5 < 10.75M fits int32
        #pragma unroll
        for (int o = 0; o < OUT; ++o) wv[i][o] = __ldg(w + o);
    }

    // ---- dedup via warp-shared hash set (overlaps with gather latency) ----
    float ms[HPT];
    #pragma unroll
    for (int i = 0; i < HPT; ++i) {
        float m = 0.0f;
        if (valid[i]) {
            const int f = fs[i];
            unsigned slot = ((unsigned)f * 0x9E3779B1u >> 23) & HASH_MASK;
            int prev = atomicCAS(&table[slot], -1, f);
            while (prev != -1 && prev != f) {
                slot = (slot + 1) & HASH_MASK;
                prev = atomicCAS(&table[slot], -1, f);
            }
            m = (prev == -1) ? 1.0f : 0.0f;   // first occurrence only
        }
        ms[i] = m;
    }

    // ---- accumulate ----
    float acc[OUT] = {0.f, 0.f, 0.f, 0.f, 0.f};
    #pragma unroll
    for (int i = 0; i < HPT; ++i) {
        #pragma unroll
        for (int o = 0; o < OUT; ++o)
            acc[o] += wv[i][o] * ms[i];
    }

    // ---- butterfly reduce: every lane ends with all 5 totals ----
    #pragma unroll
    for (int off = 16; off > 0; off >>= 1) {
        #pragma unroll
        for (int o = 0; o < OUT; ++o)
            acc[o] += __shfl_xor_sync(0xFFFFFFFFu, acc[o], off);
    }

    // ---- lanes 0..4 write their own output element ----
    if (lane < OUT) {
        float v = bv;
        #pragma unroll
        for (int o = 0; o < OUT; ++o)
            if (o == lane) v += acc[o];
        out[b * OUT + lane] = v;
    }
}

extern "C" void kernel_launch(void* const* d_in, const int* in_sizes, int n_in,
                              void* d_out, int out_size)
{
    const int*   x    = (const int*)d_in[0];
    const float* W    = (const float*)d_in[1];
    const float* bias = (const float*)d_in[2];
    float*       out  = (float*)d_out;

    prtnn_kernel<<<NB, 32>>>(x, W, bias, out);
}

// round 7
// speedup vs baseline: 1.4676x; 1.4676x over previous
#include <cuda_runtime.h>
#include <cuda_bf16.h>
#include <cstdint>

// out[b, o] = bias[o] + sum over UNIQUE (i0,i1) pairs in batch row b of
//             W[i0*350 + i1, o]
//
// Inputs (metadata order):
//   d_in[0]: x    int32  [32, 200, 3]   (b, i0, i1)
//   d_in[1]: W    float  [2150400, 5]
//   d_in[2]: b    float  [5]
// Output: float [32, 5]
//
// R4 structure (proven fastest): 224 threads / 7 warps per batch row,
// one hit per thread, hash-set dedup overlapped with speculative W gather,
// REDG atomic epilogue into bias-initialized out. R7: vectorized table init.

#define NB      32
#define NHITS   200
#define D1      350
#define OUT     5
#define TPB     224            // 7 warps
#define HASH_SZ 512
#define HASH_MASK (HASH_SZ - 1)

__global__ void __launch_bounds__(TPB, 1)
prtnn_kernel(const int* __restrict__ x,
             const float* __restrict__ W,
             const float* __restrict__ bias,
             float* __restrict__ out)
{
    const int b = blockIdx.x;
    const int t = threadIdx.x;

    __shared__ int table[HASH_SZ];

    // Issue the x load FIRST so its latency overlaps table init + barrier.
    int f = -1;
    if (t < NHITS) {
        const int* xp = x + ((size_t)b * NHITS + t) * 3;
        f = __ldg(xp + 1) * D1 + __ldg(xp + 2);   // feature = i0*350 + i1
    }

    // hash-table init: 128 int4 stores, threads 0..127 (one STS.128 each)
    if (t < HASH_SZ / 4) {
        reinterpret_cast<int4*>(table)[t] = make_int4(-1, -1, -1, -1);
    }

    // initialize this block's 5 outputs with the bias (ordered before the
    // epilogue atomics by the __syncthreads cta-scope fence)
    if (t < OUT) out[b * OUT + t] = __ldg(bias + t);

    __syncthreads();

    float acc[OUT] = {0.f, 0.f, 0.f, 0.f, 0.f};
    if (t < NHITS) {
        // Speculatively issue the W-row gather NOW (idempotent) so its memory
        // latency overlaps with the hash-based dedup below.
        const float* w = W + f * OUT;             // f*5 < 10.75M, fits int32
        float wv[OUT];
        #pragma unroll
        for (int o = 0; o < OUT; ++o) wv[o] = __ldg(w + o);

        // hash-set insert: winner of the CAS for feature f is "unique".
        unsigned slot = ((unsigned)f * 0x9E3779B1u >> 23) & HASH_MASK;
        int prev = atomicCAS(&table[slot], -1, f);
        while (prev != -1 && prev != f) {
            slot = (slot + 1) & HASH_MASK;
            prev = atomicCAS(&table[slot], -1, f);
        }
        const float m = (prev == -1) ? 1.0f : 0.0f;   // first occurrence only
        #pragma unroll
        for (int o = 0; o < OUT; ++o) acc[o] = wv[o] * m;
    }

    // warp tree-reduce the 5 partial sums
    #pragma unroll
    for (int off = 16; off > 0; off >>= 1) {
        #pragma unroll
        for (int o = 0; o < OUT; ++o)
            acc[o] += __shfl_down_sync(0xFFFFFFFFu, acc[o], off);
    }

    // lane 0 of each warp accumulates directly into global out
    // (REDG no-return; out was bias-initialized before the barrier)
    if ((t & 31) == 0) {
        #pragma unroll
        for (int o = 0; o < OUT; ++o)
            atomicAdd(&out[b * OUT + o], acc[o]);
    }
}

extern "C" void kernel_launch(void* const* d_in, const int* in_sizes, int n_in,
                              void* d_out, int out_size)
{
    const int*   x    = (const int*)d_in[0];
    const float* W    = (const float*)d_in[1];
    const float* bias = (const float*)d_in[2];
    float*       out  = (float*)d_out;

    prtnn_kernel<<<NB, TPB>>>(x, W, bias, out);
}